// round 1
// baseline (speedup 1.0000x reference)
#include <cuda_runtime.h>
#include <math.h>

#define DD 512
#define MM 2048
#define BB 4
#define KK 8
#define NN 8192
#define MB_ (MM*BB)               // 8192 floats per h_all row
#define ROWS_PER_BLOCK 8
#define NEG_INF (-1e30f)
#define EPSV 1e-8f

// Scratch (device globals: allocation-free rule)
__device__ float g_Vt[(size_t)MM*BB*DD];   // 16 MB: Vt[(m*B+b)*D + d] = V[d*M*B + m*B + b]
__device__ float g_esum[MM];               // per-expert energy sums over all rows
__device__ float g_counts[MM];             // expert selection counts
__device__ float g_acc[3];                 // 0: captured, 1: recon, 2: uncaptured (sums over rows)

__global__ void init_kernel() {
    int t = blockIdx.x * blockDim.x + threadIdx.x;
    if (t < MM) { g_esum[t] = 0.0f; g_counts[t] = 0.0f; }
    if (t < 3) g_acc[t] = 0.0f;
}

// Tiled transpose: V (D, M*B) -> Vt (M*B, D)
__global__ void transpose_kernel(const float* __restrict__ V) {
    __shared__ float tile[32][33];
    int mb0 = blockIdx.x * 32;
    int d0  = blockIdx.y * 32;
    int tx = threadIdx.x, ty = threadIdx.y;    // 32 x 8
    #pragma unroll
    for (int i = 0; i < 32; i += 8)
        tile[ty + i][tx] = V[(size_t)(d0 + ty + i) * MB_ + mb0 + tx];
    __syncthreads();
    #pragma unroll
    for (int i = 0; i < 32; i += 8)
        g_Vt[(size_t)(mb0 + ty + i) * DD + d0 + tx] = tile[tx][ty + i];
}

// Fused: energy -> top-K -> h_sparse/idx -> x_hat + residual scalars.
// One block handles ROWS_PER_BLOCK rows sequentially; 256 threads.
__global__ __launch_bounds__(256)
void main_kernel(const float* __restrict__ x_flat,
                 const float* __restrict__ h_all,
                 float* __restrict__ out) {
    __shared__ float e_sh[MM];          // 8 KB
    __shared__ float red_v[8];
    __shared__ int   red_i[8];
    __shared__ float red_a[8];
    __shared__ float red_b[8];
    __shared__ int   sel_idx[KK];
    __shared__ float sel_val[KK];
    __shared__ float hs_sh[KK * BB];

    const int t = threadIdx.x;
    const int warp = t >> 5, lane = t & 31;

    float esum[8];
    #pragma unroll
    for (int j = 0; j < 8; j++) esum[j] = 0.0f;
    float blk_cap = 0.0f, blk_rec = 0.0f, blk_unc = 0.0f;

    float* out_hs  = out;                      // (N, K, B)
    float* out_idx = out + (size_t)NN * KK * BB; // (N, K) as float

    for (int r = 0; r < ROWS_PER_BLOCK; r++) {
        const int n = blockIdx.x * ROWS_PER_BLOCK + r;
        const float4* hrow = (const float4*)(h_all + (size_t)n * MB_); // M entries of float4 (B=4)

        // ---- Phase A: energies ----
        #pragma unroll
        for (int j = 0; j < 8; j++) {
            int m = t + 256 * j;
            float4 h = hrow[m];
            float e = h.x * h.x + h.y * h.y + h.z * h.z + h.w * h.w;
            e_sh[m] = e;
            esum[j] += e;
        }
        __syncthreads();

        // ---- Phase B: top-K extraction (sorted desc, lowest-index tiebreak) ----
        for (int kk = 0; kk < KK; kk++) {
            float bv = NEG_INF; int bi = MM;
            #pragma unroll
            for (int j = 0; j < 8; j++) {
                int m = t + 256 * j;
                float v = e_sh[m];
                if (v > bv) { bv = v; bi = m; }
            }
            #pragma unroll
            for (int off = 16; off; off >>= 1) {
                float ov = __shfl_down_sync(0xffffffffu, bv, off);
                int   oi = __shfl_down_sync(0xffffffffu, bi, off);
                if (ov > bv || (ov == bv && oi < bi)) { bv = ov; bi = oi; }
            }
            if (lane == 0) { red_v[warp] = bv; red_i[warp] = bi; }
            __syncthreads();
            if (t == 0) {
                #pragma unroll
                for (int w = 1; w < 8; w++) {
                    if (red_v[w] > bv || (red_v[w] == bv && red_i[w] < bi)) {
                        bv = red_v[w]; bi = red_i[w];
                    }
                }
                sel_idx[kk] = bi; sel_val[kk] = bv;
                e_sh[bi] = NEG_INF;
            }
            __syncthreads();
        }

        // ---- Phase C: per-row outputs ----
        if (t < KK) {
            int m = sel_idx[t];
            out_idx[(size_t)n * KK + t] = (float)m;
            float4 h = hrow[m];
            ((float4*)hs_sh)[t] = h;
            ((float4*)(out_hs + (size_t)n * KK * BB))[t] = h;
            atomicAdd(&g_counts[m], 1.0f);
        }
        if (t == 0) {
            float c = 0.0f;
            #pragma unroll
            for (int kk = 0; kk < KK; kk++) c += sel_val[kk];
            blk_cap += c;
        }
        __syncthreads();

        // ---- Phase D: x_hat + residual (each thread owns 2 d's) ----
        const int d0 = 2 * t;
        float ax = 0.0f, ay = 0.0f;
        #pragma unroll
        for (int kk = 0; kk < KK; kk++) {
            const int m = sel_idx[kk];
            const float* vb = g_Vt + (size_t)m * BB * DD + d0;
            #pragma unroll
            for (int b = 0; b < BB; b++) {
                float hv = hs_sh[kk * BB + b];
                float2 v = *(const float2*)(vb + b * DD);
                ax += hv * v.x;
                ay += hv * v.y;
            }
        }
        float2 xv = *(const float2*)(x_flat + (size_t)n * DD + d0);
        float rx = xv.x - ax, ry = xv.y - ay;
        float punc = rx * rx + ry * ry;
        float prec = ax * ax + ay * ay;
        #pragma unroll
        for (int off = 16; off; off >>= 1) {
            punc += __shfl_down_sync(0xffffffffu, punc, off);
            prec += __shfl_down_sync(0xffffffffu, prec, off);
        }
        if (lane == 0) { red_a[warp] = punc; red_b[warp] = prec; }
        __syncthreads();
        if (t == 0) {
            float su = 0.0f, sr = 0.0f;
            #pragma unroll
            for (int w = 0; w < 8; w++) { su += red_a[w]; sr += red_b[w]; }
            blk_unc += su; blk_rec += sr;
        }
        __syncthreads();
    }

    // ---- block-level accumulator flush ----
    #pragma unroll
    for (int j = 0; j < 8; j++)
        atomicAdd(&g_esum[t + 256 * j], esum[j]);
    if (t == 0) {
        atomicAdd(&g_acc[0], blk_cap);
        atomicAdd(&g_acc[1], blk_rec);
        atomicAdd(&g_acc[2], blk_unc);
    }
}

// Single-block finalize: entropy, dead-expert counts, write 7 scalars.
__global__ void final_kernel(float* __restrict__ out) {
    __shared__ float red[8];
    __shared__ float s_denom;
    const int t = threadIdx.x;
    const int warp = t >> 5, lane = t & 31;

    // total energy sum -> denom
    float s = 0.0f;
    #pragma unroll
    for (int j = 0; j < 8; j++) s += g_esum[t + 256 * j];
    #pragma unroll
    for (int off = 16; off; off >>= 1) s += __shfl_down_sync(0xffffffffu, s, off);
    if (lane == 0) red[warp] = s;
    __syncthreads();
    if (t == 0) {
        float tot = 0.0f;
        #pragma unroll
        for (int w = 0; w < 8; w++) tot += red[w];
        s_denom = fmaxf(tot / (float)NN, EPSV);
    }
    __syncthreads();
    const float denom = s_denom;

    float ent = 0.0f, low = 0.0f, dead = 0.0f;
    const float expected = (float)KK / (float)MM * (float)NN;  // 32
    #pragma unroll
    for (int j = 0; j < 8; j++) {
        int m = t + 256 * j;
        float avg = g_esum[m] / (float)NN;
        float p = fmaxf(avg / denom, EPSV);
        ent += -p * logf(p);
        float c = g_counts[m];
        if (c <= 0.1f * expected)  low  += 1.0f;
        if (c <= 0.01f * expected) dead += 1.0f;
    }
    #pragma unroll
    for (int off = 16; off; off >>= 1) {
        ent  += __shfl_down_sync(0xffffffffu, ent,  off);
        low  += __shfl_down_sync(0xffffffffu, low,  off);
        dead += __shfl_down_sync(0xffffffffu, dead, off);
    }
    __shared__ float re[8], rl[8], rd[8];
    if (lane == 0) { re[warp] = ent; rl[warp] = low; rd[warp] = dead; }
    __syncthreads();
    if (t == 0) {
        float E = 0.0f, L = 0.0f, Dd = 0.0f;
        #pragma unroll
        for (int w = 0; w < 8; w++) { E += re[w]; L += rl[w]; Dd += rd[w]; }
        float entropy = E / logf((float)MM);
        float cap = g_acc[0] / (float)NN;
        float rec = g_acc[1] / (float)NN;
        float unc = g_acc[2] / (float)NN;
        size_t OFF = (size_t)NN * KK * BB + (size_t)NN * KK;  // 327680
        out[OFF + 0] = cap;
        out[OFF + 1] = rec;
        out[OFF + 2] = unc;
        out[OFF + 3] = entropy;
        out[OFF + 4] = unc + 0.01f * (1.0f - entropy);
        out[OFF + 5] = L;
        out[OFF + 6] = Dd;
    }
}

extern "C" void kernel_launch(void* const* d_in, const int* in_sizes, int n_in,
                              void* d_out, int out_size) {
    const float* x_flat = (const float*)d_in[0];   // (N, D)
    const float* h_all  = (const float*)d_in[1];   // (N, M, B)
    const float* V      = (const float*)d_in[2];   // (D, M, B)
    float* out = (float*)d_out;

    init_kernel<<<8, 256>>>();

    dim3 tb(32, 8);
    dim3 tg(MB_ / 32, DD / 32);    // (256, 16)
    transpose_kernel<<<tg, tb>>>(V);

    main_kernel<<<NN / ROWS_PER_BLOCK, 256>>>(x_flat, h_all, out);

    final_kernel<<<1, 256>>>(out);
}